// round 1
// baseline (speedup 1.0000x reference)
#include <cuda_runtime.h>
#include <math.h>

// ---------------------------------------------------------------------------
// TimeMix (RWKV-style): B=4, S=4096, D=2048
//   r = sigmoid(x@Wr^T); w = -exp(x@Ww^T); k = x@Wk^T; v = x@Wv^T
//   ewk = exp(w+k); per-channel scan over S with decay=exp(time_decay)
//   out = (r*wkv)@Wo^T ; final_state = [num, den] per (b, d)
// ---------------------------------------------------------------------------

namespace {
constexpr int kB = 4;
constexpr int kS = 4096;
constexpr int kD = 2048;
constexpr int kM = kB * kS;          // 16384
constexpr int kChunks = 64;
constexpr int kCLen = kS / kChunks;  // 64

constexpr int BM = 128, BN = 128, BK = 16;
}  // namespace

// Scratch (device globals: allocation APIs are forbidden)
__device__ float g_r[kM * kD];
__device__ float g_w[kM * kD];
__device__ float g_ewk[kM * kD];
__device__ float g_v[kM * kD];
__device__ float g_y[kM * kD];
__device__ float g_cnum[kChunks * kB * kD];
__device__ float g_cden[kChunks * kB * kD];
__device__ float g_inum[kChunks * kB * kD];
__device__ float g_iden[kChunks * kB * kD];

enum { ACT_NONE = 0, ACT_SIGMOID = 1, ACT_EWK = 2 };

// ---------------------------------------------------------------------------
// SGEMM: Cmat[m,n] = act( sum_k A[m,k] * W[n,k] ),  K = kD fixed.
// 128x128 tile, BK=16, 256 threads, 8x8 per thread, register prefetch.
// ---------------------------------------------------------------------------
__global__ __launch_bounds__(256, 2) void sgemm_act(
    const float* __restrict__ A, const float* __restrict__ W,
    float* __restrict__ Cmat, const float* __restrict__ aux, int act) {
  __shared__ float As[BK][BM + 4];
  __shared__ float Bs[BK][BN + 4];

  const int tid = threadIdx.x;
  const int tx = tid & 15;   // 0..15 -> n micro-tile
  const int ty = tid >> 4;   // 0..15 -> m micro-tile
  const int mBase = blockIdx.y * BM;
  const int nBase = blockIdx.x * BN;
  const int lrow = tid >> 2;        // 0..63
  const int lk = (tid & 3) * 4;     // 0,4,8,12

  const float* Aptr = A + (mBase + lrow) * kD + lk;
  const float* Wptr = W + (nBase + lrow) * kD + lk;

  float4 pa0 = *(const float4*)(Aptr);
  float4 pa1 = *(const float4*)(Aptr + 64 * kD);
  float4 pb0 = *(const float4*)(Wptr);
  float4 pb1 = *(const float4*)(Wptr + 64 * kD);

  float acc[8][8];
#pragma unroll
  for (int i = 0; i < 8; i++)
#pragma unroll
    for (int j = 0; j < 8; j++) acc[i][j] = 0.f;

  for (int k0 = 0; k0 < kD; k0 += BK) {
    // Commit prefetched tile to shared (transposed: [k][m] / [k][n])
    As[lk + 0][lrow] = pa0.x; As[lk + 1][lrow] = pa0.y;
    As[lk + 2][lrow] = pa0.z; As[lk + 3][lrow] = pa0.w;
    As[lk + 0][lrow + 64] = pa1.x; As[lk + 1][lrow + 64] = pa1.y;
    As[lk + 2][lrow + 64] = pa1.z; As[lk + 3][lrow + 64] = pa1.w;
    Bs[lk + 0][lrow] = pb0.x; Bs[lk + 1][lrow] = pb0.y;
    Bs[lk + 2][lrow] = pb0.z; Bs[lk + 3][lrow] = pb0.w;
    Bs[lk + 0][lrow + 64] = pb1.x; Bs[lk + 1][lrow + 64] = pb1.y;
    Bs[lk + 2][lrow + 64] = pb1.z; Bs[lk + 3][lrow + 64] = pb1.w;
    __syncthreads();

    if (k0 + BK < kD) {  // prefetch next K-slab while computing
      Aptr += BK; Wptr += BK;
      pa0 = *(const float4*)(Aptr);
      pa1 = *(const float4*)(Aptr + 64 * kD);
      pb0 = *(const float4*)(Wptr);
      pb1 = *(const float4*)(Wptr + 64 * kD);
    }

#pragma unroll
    for (int kk = 0; kk < BK; kk++) {
      float ra[8], rb[8];
      *(float4*)&ra[0] = *(const float4*)&As[kk][ty * 8];
      *(float4*)&ra[4] = *(const float4*)&As[kk][ty * 8 + 4];
      *(float4*)&rb[0] = *(const float4*)&Bs[kk][tx * 8];
      *(float4*)&rb[4] = *(const float4*)&Bs[kk][tx * 8 + 4];
#pragma unroll
      for (int i = 0; i < 8; i++)
#pragma unroll
        for (int j = 0; j < 8; j++) acc[i][j] = fmaf(ra[i], rb[j], acc[i][j]);
    }
    __syncthreads();
  }

  // Epilogue with fused activation; vectorized stores.
#pragma unroll
  for (int i = 0; i < 8; i++) {
    const int m = mBase + ty * 8 + i;
    const int ncol = nBase + tx * 8;
#pragma unroll
    for (int jq = 0; jq < 2; jq++) {
      float4 o;
      float vals[4];
#pragma unroll
      for (int j = 0; j < 4; j++) vals[j] = acc[i][jq * 4 + j];
      if (act == ACT_SIGMOID) {
#pragma unroll
        for (int j = 0; j < 4; j++) vals[j] = 1.f / (1.f + expf(-vals[j]));
      } else if (act == ACT_EWK) {
        float4 wv = *(const float4*)&aux[m * kD + ncol + jq * 4];
        vals[0] = expf(vals[0] - expf(wv.x));
        vals[1] = expf(vals[1] - expf(wv.y));
        vals[2] = expf(vals[2] - expf(wv.z));
        vals[3] = expf(vals[3] - expf(wv.w));
      }
      o.x = vals[0]; o.y = vals[1]; o.z = vals[2]; o.w = vals[3];
      *(float4*)&Cmat[m * kD + ncol + jq * 4] = o;
    }
  }
}

// ---------------------------------------------------------------------------
// Pass A: per-chunk local scan (zero init) -> chunk-end (num, den)
// grid: (kD/256, kB, kChunks), block 256. Coalesced over d.
// ---------------------------------------------------------------------------
__global__ __launch_bounds__(256) void scan_partial(const float* __restrict__ td) {
  const int e = blockIdx.x * 256 + threadIdx.x;
  const int b = blockIdx.y;
  const int c = blockIdx.z;
  const float dec = expf(td[e]);
  float num = 0.f, den = 0.f;
  int base = (b * kS + c * kCLen) * kD + e;
#pragma unroll 4
  for (int i = 0; i < kCLen; i++) {
    const float ew = g_ewk[base];
    const float vv = g_v[base];
    num = dec * num + ew * vv;
    den = dec * den + ew;
    base += kD;
  }
  const int ci = (c * kB + b) * kD + e;
  g_cnum[ci] = num;
  g_cden[ci] = den;
}

// ---------------------------------------------------------------------------
// Pass B: cross-chunk carry scan; also writes final_state into d_out tail.
// grid: (kD/256, kB), block 256.
// ---------------------------------------------------------------------------
__global__ __launch_bounds__(256) void scan_carry(const float* __restrict__ td,
                                                  float* __restrict__ out) {
  const int e = blockIdx.x * 256 + threadIdx.x;
  const int b = blockIdx.y;
  const float decL = expf(td[e] * (float)kCLen);  // decay^kCLen
  float num = 0.f, den = 0.f;
#pragma unroll 8
  for (int c = 0; c < kChunks; c++) {
    const int ci = (c * kB + b) * kD + e;
    g_inum[ci] = num;  // carry-in to chunk c
    g_iden[ci] = den;
    num = decL * num + g_cnum[ci];
    den = decL * den + g_cden[ci];
  }
  // final_state [B, 2, D] appended after out [B, S, D]
  float* fs = out + (size_t)kM * kD;
  fs[b * 2 * kD + e] = num;
  fs[b * 2 * kD + kD + e] = den;
}

// ---------------------------------------------------------------------------
// Pass C: rescan with carry-in, emit y = r * (num / (den + 1e-8)).
// ---------------------------------------------------------------------------
__global__ __launch_bounds__(256) void scan_final(const float* __restrict__ td) {
  const int e = blockIdx.x * 256 + threadIdx.x;
  const int b = blockIdx.y;
  const int c = blockIdx.z;
  const float dec = expf(td[e]);
  const int ci = (c * kB + b) * kD + e;
  float num = g_inum[ci];
  float den = g_iden[ci];
  int base = (b * kS + c * kCLen) * kD + e;
#pragma unroll 4
  for (int i = 0; i < kCLen; i++) {
    const float ew = g_ewk[base];
    const float vv = g_v[base];
    const float rr = g_r[base];
    num = dec * num + ew * vv;
    den = dec * den + ew;
    const float wkv = num / (den + 1e-8f);
    g_y[base] = rr * wkv;
    base += kD;
  }
}

// ---------------------------------------------------------------------------
extern "C" void kernel_launch(void* const* d_in, const int* in_sizes, int n_in,
                              void* d_out, int out_size) {
  const float* x  = (const float*)d_in[0];
  const float* Wr = (const float*)d_in[1];
  const float* Ww = (const float*)d_in[2];
  const float* Wk = (const float*)d_in[3];
  const float* Wv = (const float*)d_in[4];
  const float* Wo = (const float*)d_in[5];
  const float* td = (const float*)d_in[6];
  float* out = (float*)d_out;

  float *pr, *pw, *pe, *pv, *py;
  cudaGetSymbolAddress((void**)&pr, g_r);
  cudaGetSymbolAddress((void**)&pw, g_w);
  cudaGetSymbolAddress((void**)&pe, g_ewk);
  cudaGetSymbolAddress((void**)&pv, g_v);
  cudaGetSymbolAddress((void**)&py, g_y);

  dim3 gg(kD / BN, kM / BM);  // (16, 128)

  // Projections (w before k: k's epilogue fuses ewk = exp(k - exp(w)))
  sgemm_act<<<gg, 256>>>(x, Wr, pr, nullptr, ACT_SIGMOID);
  sgemm_act<<<gg, 256>>>(x, Ww, pw, nullptr, ACT_NONE);
  sgemm_act<<<gg, 256>>>(x, Wk, pe, pw, ACT_EWK);
  sgemm_act<<<gg, 256>>>(x, Wv, pv, nullptr, ACT_NONE);

  // Chunked linear-recurrence scan
  dim3 gs(kD / 256, kB, kChunks);
  scan_partial<<<gs, 256>>>(td);
  scan_carry<<<dim3(kD / 256, kB), 256>>>(td, out);
  scan_final<<<gs, 256>>>(td);

  // Output projection
  sgemm_act<<<gg, 256>>>(py, Wo, out, nullptr, ACT_NONE);
}

// round 3
// speedup vs baseline: 6.3620x; 6.3620x over previous
#include <cuda_runtime.h>
#include <cuda_fp16.h>
#include <math.h>
#include <stdint.h>

// ---------------------------------------------------------------------------
// TimeMix (RWKV-style): B=4, S=4096, D=2048 — fp16 mma.sync (HMMA) edition.
// tcgen05 is unavailable: harness PTX targets sm_103 (no 'a' features).
// ---------------------------------------------------------------------------

namespace {
constexpr int kB = 4;
constexpr int kS = 4096;
constexpr int kD = 2048;
constexpr int kM = kB * kS;          // 16384
constexpr int kChunks = 64;
constexpr int kCLen = kS / kChunks;  // 64

constexpr int BM = 128, BN = 128, BKH = 64;        // BKH halves = 128 B rows
constexpr int NSTAGE = 3;
constexpr int KSTAGES = kD / BKH;                  // 32
constexpr uint32_t A_BYTES = BM * 128;             // 16384
constexpr uint32_t STAGE_BYTES = 2 * A_BYTES;      // A + B = 32768
constexpr uint32_t SMEM_BYTES = NSTAGE * STAGE_BYTES;  // 98304
}  // namespace

// Scratch (device globals; allocation APIs forbidden)
__device__ float g_r[kM * kD];
__device__ float g_w[kM * kD];
__device__ float g_ewk[kM * kD];
__device__ float g_v[kM * kD];
__device__ float g_y[kM * kD];
__device__ float g_cnum[kChunks * kB * kD];
__device__ float g_cden[kChunks * kB * kD];
__device__ float g_inum[kChunks * kB * kD];
__device__ float g_iden[kChunks * kB * kD];
__device__ __align__(16) __half g_xh[kM * kD];
__device__ __align__(16) __half g_yh[kM * kD];
__device__ __align__(16) __half g_wh[5][kD * kD];

enum { ACT_NONE = 0, ACT_SIGMOID = 1, ACT_EWK = 2 };

// ------------------------------- asm helpers -------------------------------
__device__ __forceinline__ uint32_t smem_u32(const void* p) {
  uint32_t a;
  asm("{ .reg .u64 t; cvta.to.shared.u64 t, %1; cvt.u32.u64 %0, t; }"
      : "=r"(a) : "l"(p));
  return a;
}
__device__ __forceinline__ void cp16(uint32_t dst, const void* src) {
  asm volatile("cp.async.cg.shared.global [%0], [%1], 16;" :: "r"(dst), "l"(src));
}
#define CP_COMMIT() asm volatile("cp.async.commit_group;" ::: "memory")
#define CP_WAIT1() asm volatile("cp.async.wait_group 1;" ::: "memory")

#define LDM_X4(r0, r1, r2, r3, addr)                                        \
  asm volatile("ldmatrix.sync.aligned.m8n8.x4.shared.b16 {%0,%1,%2,%3}, [%4];" \
               : "=r"(r0), "=r"(r1), "=r"(r2), "=r"(r3) : "r"(addr))

#define MMA16816(d, a, b)                                                   \
  asm volatile(                                                             \
      "mma.sync.aligned.m16n8k16.row.col.f32.f16.f16.f32 "                  \
      "{%0,%1,%2,%3}, {%4,%5,%6,%7}, {%8,%9}, {%0,%1,%2,%3};"               \
      : "+f"(d[0]), "+f"(d[1]), "+f"(d[2]), "+f"(d[3])                      \
      : "r"(a[0]), "r"(a[1]), "r"(a[2]), "r"(a[3]), "r"(b[0]), "r"(b[1]))

__device__ __forceinline__ uint32_t swz(uint32_t off) {
  return off ^ ((off >> 3) & 0x70);
}

// Fill one stage: A tile 128 rows x 128 B, B tile 128 rows x 128 B. SW128.
__device__ __forceinline__ void stage_fill(uint32_t slotbase, const __half* A,
                                           const __half* W, int mBase,
                                           int nBase, int k0, int tid) {
#pragma unroll
  for (int t = 0; t < 8; t++) {
    const int idx = tid + t * 256;      // 0..2047
    const int row = (idx & 1023) >> 3;  // 0..127
    const int j = idx & 7;              // 16B chunk in row
    const __half* src;
    uint32_t dstBase;
    if (idx < 1024) {
      src = A + (size_t)(mBase + row) * kD;
      dstBase = slotbase;
    } else {
      src = W + (size_t)(nBase + row) * kD;
      dstBase = slotbase + A_BYTES;
    }
    const uint32_t off = (uint32_t)row * 128u + (uint32_t)j * 16u;
    cp16(dstBase + swz(off), src + k0 + j * 8);
  }
}

// ---------------------------------------------------------------------------
// HMMA GEMM: C[m,n] = act( sum_k A[m,k] * W[n,k] ), fp16 in, fp32 accumulate.
// CTA 128x128, warps 2(M)x4(N) -> 64x32 warp tiles, mma m16n8k16.
// ---------------------------------------------------------------------------
__global__ __launch_bounds__(256) void gemm_hmma(const __half* __restrict__ A,
                                                 const __half* __restrict__ W,
                                                 float* __restrict__ C,
                                                 const float* __restrict__ aux,
                                                 int act) {
  extern __shared__ char smem[];
  const uint32_t sb = smem_u32(smem);
  const int tid = threadIdx.x;
  const int wid = tid >> 5;
  const int lid = tid & 31;
  const int mBase = blockIdx.y * BM;
  const int nBase = blockIdx.x * BN;
  const int warp_m = (wid & 1) * 64;
  const int warp_n = (wid >> 1) * 32;

  float acc[4][4][4];
#pragma unroll
  for (int a = 0; a < 4; a++)
#pragma unroll
    for (int b = 0; b < 4; b++)
#pragma unroll
      for (int c = 0; c < 4; c++) acc[a][b][c] = 0.f;

  // Prologue: 2 stages in flight
  stage_fill(sb, A, W, mBase, nBase, 0, tid);
  CP_COMMIT();
  stage_fill(sb + STAGE_BYTES, A, W, mBase, nBase, BKH, tid);
  CP_COMMIT();

  // Precomputed ldmatrix lane geometry
  const int am = lid >> 3;                       // matrix id 0..3
  const int a_row = ((am & 1) * 8) + (lid & 7);  // A: +8 for odd matrices
  const int a_kb = (am >> 1) * 16;               // A: k-chunk for matrices 2,3
  const int b_row = ((am >> 1) * 8) + (lid & 7); // B: +8 for matrices 2,3
  const int b_kb = (am & 1) * 16;                // B: k-chunk for odd matrices

  for (int i = 0; i < KSTAGES; i++) {
    CP_WAIT1();
    __syncthreads();
    const int nslot = i + 2;
    if (nslot < KSTAGES)
      stage_fill(sb + (nslot % NSTAGE) * STAGE_BYTES, A, W, mBase, nBase,
                 nslot * BKH, tid);
    CP_COMMIT();

    const uint32_t sA = sb + (i % NSTAGE) * STAGE_BYTES;
    const uint32_t sB = sA + A_BYTES;
#pragma unroll
    for (int ks = 0; ks < 4; ks++) {
      uint32_t af[4][4];
#pragma unroll
      for (int mf = 0; mf < 4; mf++) {
        const uint32_t off =
            (uint32_t)(warp_m + mf * 16 + a_row) * 128u + ks * 32 + a_kb;
        LDM_X4(af[mf][0], af[mf][1], af[mf][2], af[mf][3], sA + swz(off));
      }
      uint32_t bf[4][2];
#pragma unroll
      for (int nf2 = 0; nf2 < 2; nf2++) {
        const uint32_t off =
            (uint32_t)(warp_n + nf2 * 16 + b_row) * 128u + ks * 32 + b_kb;
        uint32_t t0, t1, t2, t3;
        LDM_X4(t0, t1, t2, t3, sB + swz(off));
        bf[nf2 * 2][0] = t0;
        bf[nf2 * 2][1] = t1;
        bf[nf2 * 2 + 1][0] = t2;
        bf[nf2 * 2 + 1][1] = t3;
      }
#pragma unroll
      for (int mf = 0; mf < 4; mf++)
#pragma unroll
        for (int nf = 0; nf < 4; nf++) MMA16816(acc[mf][nf], af[mf], bf[nf]);
    }
  }

  // Epilogue: fragment layout -> direct float2 stores with fused activation.
#pragma unroll
  for (int mf = 0; mf < 4; mf++) {
    const int r0 = mBase + warp_m + mf * 16 + (lid >> 2);
#pragma unroll
    for (int nf = 0; nf < 4; nf++) {
      const int cc = nBase + warp_n + nf * 8 + (lid & 3) * 2;
      float v[4] = {acc[mf][nf][0], acc[mf][nf][1], acc[mf][nf][2],
                    acc[mf][nf][3]};
      if (act == ACT_SIGMOID) {
#pragma unroll
        for (int q = 0; q < 4; q++) v[q] = 1.f / (1.f + expf(-v[q]));
      } else if (act == ACT_EWK) {
        const float2 w0 = *(const float2*)&aux[(size_t)r0 * kD + cc];
        const float2 w1 = *(const float2*)&aux[(size_t)(r0 + 8) * kD + cc];
        v[0] = expf(v[0] - expf(w0.x));
        v[1] = expf(v[1] - expf(w0.y));
        v[2] = expf(v[2] - expf(w1.x));
        v[3] = expf(v[3] - expf(w1.y));
      }
      *(float2*)&C[(size_t)r0 * kD + cc] = make_float2(v[0], v[1]);
      *(float2*)&C[(size_t)(r0 + 8) * kD + cc] = make_float2(v[2], v[3]);
    }
  }
}

// ------------------------------ fp32 -> fp16 -------------------------------
__global__ __launch_bounds__(256) void cvt_f2h(const float* __restrict__ s,
                                               __half2* __restrict__ d, int n4) {
  int i = blockIdx.x * blockDim.x + threadIdx.x;
  const int stride = gridDim.x * blockDim.x;
  for (; i < n4; i += stride) {
    const float4 v = ((const float4*)s)[i];
    d[2 * i] = __floats2half2_rn(v.x, v.y);
    d[2 * i + 1] = __floats2half2_rn(v.z, v.w);
  }
}

// ------------------------------- scan kernels ------------------------------
__global__ __launch_bounds__(256) void scan_partial(const float* __restrict__ td) {
  const int e = blockIdx.x * 256 + threadIdx.x;
  const int b = blockIdx.y;
  const int c = blockIdx.z;
  const float dec = expf(td[e]);
  float num = 0.f, den = 0.f;
  int base = (b * kS + c * kCLen) * kD + e;
#pragma unroll 4
  for (int i = 0; i < kCLen; i++) {
    const float ew = g_ewk[base];
    const float vv = g_v[base];
    num = dec * num + ew * vv;
    den = dec * den + ew;
    base += kD;
  }
  const int ci = (c * kB + b) * kD + e;
  g_cnum[ci] = num;
  g_cden[ci] = den;
}

__global__ __launch_bounds__(256) void scan_carry(const float* __restrict__ td,
                                                  float* __restrict__ out) {
  const int e = blockIdx.x * 256 + threadIdx.x;
  const int b = blockIdx.y;
  const float decL = expf(td[e] * (float)kCLen);
  float num = 0.f, den = 0.f;
#pragma unroll 8
  for (int c = 0; c < kChunks; c++) {
    const int ci = (c * kB + b) * kD + e;
    g_inum[ci] = num;
    g_iden[ci] = den;
    num = decL * num + g_cnum[ci];
    den = decL * den + g_cden[ci];
  }
  float* fs = out + (size_t)kM * kD;
  fs[b * 2 * kD + e] = num;
  fs[b * 2 * kD + kD + e] = den;
}

__global__ __launch_bounds__(256) void scan_final(const float* __restrict__ td) {
  const int e = blockIdx.x * 256 + threadIdx.x;
  const int b = blockIdx.y;
  const int c = blockIdx.z;
  const float dec = expf(td[e]);
  const int ci = (c * kB + b) * kD + e;
  float num = g_inum[ci];
  float den = g_iden[ci];
  int base = (b * kS + c * kCLen) * kD + e;
#pragma unroll 4
  for (int i = 0; i < kCLen; i++) {
    const float ew = g_ewk[base];
    const float vv = g_v[base];
    const float rr = g_r[base];
    num = dec * num + ew * vv;
    den = dec * den + ew;
    const float wkv = num / (den + 1e-8f);
    g_y[base] = rr * wkv;
    base += kD;
  }
}

// ---------------------------------------------------------------------------
extern "C" void kernel_launch(void* const* d_in, const int* in_sizes, int n_in,
                              void* d_out, int out_size) {
  const float* x = (const float*)d_in[0];
  const float* Wf[5] = {(const float*)d_in[1], (const float*)d_in[2],
                        (const float*)d_in[3], (const float*)d_in[4],
                        (const float*)d_in[5]};
  const float* td = (const float*)d_in[6];
  float* out = (float*)d_out;

  float *pr, *pw, *pe, *pv, *py;
  cudaGetSymbolAddress((void**)&pr, g_r);
  cudaGetSymbolAddress((void**)&pw, g_w);
  cudaGetSymbolAddress((void**)&pe, g_ewk);
  cudaGetSymbolAddress((void**)&pv, g_v);
  cudaGetSymbolAddress((void**)&py, g_y);
  __half *xh, *yh, *wh;
  cudaGetSymbolAddress((void**)&xh, g_xh);
  cudaGetSymbolAddress((void**)&yh, g_yh);
  cudaGetSymbolAddress((void**)&wh, g_wh);

  cudaFuncSetAttribute(gemm_hmma, cudaFuncAttributeMaxDynamicSharedMemorySize,
                       SMEM_BYTES);

  // fp32 -> fp16 conversions
  cvt_f2h<<<4096, 256>>>(x, (__half2*)xh, kM * kD / 4);
  for (int i = 0; i < 5; i++)
    cvt_f2h<<<2048, 256>>>(Wf[i], (__half2*)(wh + (size_t)i * kD * kD),
                           kD * kD / 4);

  dim3 gg(kD / BN, kM / BM);  // (16, 128)
  const __half* Wr = wh + 0 * (size_t)kD * kD;
  const __half* Ww = wh + 1 * (size_t)kD * kD;
  const __half* Wk = wh + 2 * (size_t)kD * kD;
  const __half* Wv = wh + 3 * (size_t)kD * kD;
  const __half* Wo = wh + 4 * (size_t)kD * kD;

  gemm_hmma<<<gg, 256, SMEM_BYTES>>>(xh, Wr, pr, nullptr, ACT_SIGMOID);
  gemm_hmma<<<gg, 256, SMEM_BYTES>>>(xh, Ww, pw, nullptr, ACT_NONE);
  gemm_hmma<<<gg, 256, SMEM_BYTES>>>(xh, Wk, pe, pw, ACT_EWK);
  gemm_hmma<<<gg, 256, SMEM_BYTES>>>(xh, Wv, pv, nullptr, ACT_NONE);

  dim3 gs(kD / 256, kB, kChunks);
  scan_partial<<<gs, 256>>>(td);
  scan_carry<<<dim3(kD / 256, kB), 256>>>(td, out);
  scan_final<<<gs, 256>>>(td);

  cvt_f2h<<<4096, 256>>>(py, (__half2*)yh, kM * kD / 4);
  gemm_hmma<<<gg, 256, SMEM_BYTES>>>(yh, Wo, out, nullptr, ACT_NONE);
}

// round 4
// speedup vs baseline: 7.6198x; 1.1977x over previous
#include <cuda_runtime.h>
#include <cuda_fp16.h>
#include <math.h>
#include <stdint.h>

// ---------------------------------------------------------------------------
// TimeMix (RWKV-style): B=4, S=4096, D=2048 — fp16 mma.sync, 64x64 warp tiles
// ---------------------------------------------------------------------------

namespace {
constexpr int kB = 4;
constexpr int kS = 4096;
constexpr int kD = 2048;
constexpr int kM = kB * kS;          // 16384
constexpr int kChunks = 64;
constexpr int kCLen = kS / kChunks;  // 64

constexpr int BM = 128, BN = 128, BKH = 64;        // BKH halves = 128 B rows
constexpr int NTHR = 128;                          // 4 warps, 2x2 of 64x64
constexpr int NSTAGE = 3;
constexpr int KSTAGES = kD / BKH;                  // 32
constexpr uint32_t A_BYTES = BM * 128;             // 16384
constexpr uint32_t STAGE_BYTES = 2 * A_BYTES;      // 32768
constexpr uint32_t SMEM_BYTES = NSTAGE * STAGE_BYTES;  // 98304
}  // namespace

// Scratch (device globals; allocation APIs forbidden)
__device__ float g_r[kM * kD];
__device__ float g_w[kM * kD];
__device__ float g_ewk[kM * kD];
__device__ float g_v[kM * kD];
__device__ float g_cnum[kChunks * kB * kD];
__device__ float g_cden[kChunks * kB * kD];
__device__ float g_inum[kChunks * kB * kD];
__device__ float g_iden[kChunks * kB * kD];
__device__ __align__(16) __half g_xh[kM * kD];
__device__ __align__(16) __half g_yh[kM * kD];
__device__ __align__(16) __half g_wh[5][kD * kD];

enum { ACT_NONE = 0, ACT_SIGMOID = 1, ACT_EWK = 2 };

// ------------------------------- asm helpers -------------------------------
__device__ __forceinline__ uint32_t smem_u32(const void* p) {
  uint32_t a;
  asm("{ .reg .u64 t; cvta.to.shared.u64 t, %1; cvt.u32.u64 %0, t; }"
      : "=r"(a) : "l"(p));
  return a;
}
__device__ __forceinline__ void cp16(uint32_t dst, const void* src) {
  asm volatile("cp.async.cg.shared.global [%0], [%1], 16;" :: "r"(dst), "l"(src));
}
#define CP_COMMIT() asm volatile("cp.async.commit_group;" ::: "memory")
#define CP_WAIT1() asm volatile("cp.async.wait_group 1;" ::: "memory")

#define LDM_X4(r0, r1, r2, r3, addr)                                           \
  asm volatile("ldmatrix.sync.aligned.m8n8.x4.shared.b16 {%0,%1,%2,%3}, [%4];" \
               : "=r"(r0), "=r"(r1), "=r"(r2), "=r"(r3) : "r"(addr))

#define MMA16816(d, a, b)                                                   \
  asm volatile(                                                             \
      "mma.sync.aligned.m16n8k16.row.col.f32.f16.f16.f32 "                  \
      "{%0,%1,%2,%3}, {%4,%5,%6,%7}, {%8,%9}, {%0,%1,%2,%3};"               \
      : "+f"(d[0]), "+f"(d[1]), "+f"(d[2]), "+f"(d[3])                      \
      : "r"(a[0]), "r"(a[1]), "r"(a[2]), "r"(a[3]), "r"(b[0]), "r"(b[1]))

__device__ __forceinline__ uint32_t swz(uint32_t off) {
  return off ^ ((off >> 3) & 0x70);
}

// Fill one stage: A tile 128 x 128B, B tile 128 x 128B. K-major, SW128.
__device__ __forceinline__ void stage_fill(uint32_t slotbase, const __half* A,
                                           const __half* W, int mBase,
                                           int nBase, int k0, int tid) {
#pragma unroll
  for (int t = 0; t < 16; t++) {
    const int idx = tid + t * NTHR;     // 0..2047
    const int row = (idx & 1023) >> 3;  // 0..127
    const int j = idx & 7;              // 16B chunk in row
    const __half* src;
    uint32_t dstBase;
    if (idx < 1024) {
      src = A + (size_t)(mBase + row) * kD;
      dstBase = slotbase;
    } else {
      src = W + (size_t)(nBase + row) * kD;
      dstBase = slotbase + A_BYTES;
    }
    const uint32_t off = (uint32_t)row * 128u + (uint32_t)j * 16u;
    cp16(dstBase + swz(off), src + k0 + j * 8);
  }
}

// ---------------------------------------------------------------------------
// HMMA GEMM: C[m,n] = act( sum_k A[m,k] * W[n,k] ), fp16 in, fp32 accum.
// CTA 128x128, 4 warps 2(M)x2(N), 64x64 warp tiles, mma m16n8k16.
// ---------------------------------------------------------------------------
__global__ __launch_bounds__(NTHR, 2) void gemm_hmma(
    const __half* __restrict__ A, const __half* __restrict__ W,
    float* __restrict__ C, const float* __restrict__ aux, int act) {
  extern __shared__ char smem[];
  const uint32_t sb = smem_u32(smem);
  const int tid = threadIdx.x;
  const int wid = tid >> 5;
  const int lid = tid & 31;
  const int mBase = blockIdx.y * BM;
  const int nBase = blockIdx.x * BN;
  const int warp_m = (wid & 1) * 64;
  const int warp_n = (wid >> 1) * 64;

  float acc[4][8][4];
#pragma unroll
  for (int a = 0; a < 4; a++)
#pragma unroll
    for (int b = 0; b < 8; b++)
#pragma unroll
      for (int c = 0; c < 4; c++) acc[a][b][c] = 0.f;

  stage_fill(sb, A, W, mBase, nBase, 0, tid);
  CP_COMMIT();
  stage_fill(sb + STAGE_BYTES, A, W, mBase, nBase, BKH, tid);
  CP_COMMIT();

  // ldmatrix lane geometry
  const int am = lid >> 3;                        // matrix id 0..3
  const int a_row = ((am & 1) * 8) + (lid & 7);   // A rows
  const int a_kb = (am >> 1) * 16;                // A k8 byte offset
  const int b_row = ((am >> 1) * 8) + (lid & 7);  // B rows (n)
  const int b_kb = (am & 1) * 16;                 // B k8 byte offset

  for (int i = 0; i < KSTAGES; i++) {
    CP_WAIT1();
    __syncthreads();
    const int nslot = i + 2;
    if (nslot < KSTAGES)
      stage_fill(sb + (nslot % NSTAGE) * STAGE_BYTES, A, W, mBase, nBase,
                 nslot * BKH, tid);
    CP_COMMIT();

    const uint32_t sA = sb + (i % NSTAGE) * STAGE_BYTES;
    const uint32_t sB = sA + A_BYTES;
#pragma unroll
    for (int ks = 0; ks < 4; ks++) {
      uint32_t af[4][4];
#pragma unroll
      for (int mf = 0; mf < 4; mf++) {
        const uint32_t off =
            (uint32_t)(warp_m + mf * 16 + a_row) * 128u + ks * 32 + a_kb;
        LDM_X4(af[mf][0], af[mf][1], af[mf][2], af[mf][3], sA + swz(off));
      }
      uint32_t bf[8][2];
#pragma unroll
      for (int nf2 = 0; nf2 < 4; nf2++) {
        const uint32_t off =
            (uint32_t)(warp_n + nf2 * 16 + b_row) * 128u + ks * 32 + b_kb;
        uint32_t t0, t1, t2, t3;
        LDM_X4(t0, t1, t2, t3, sB + swz(off));
        bf[nf2 * 2][0] = t0;
        bf[nf2 * 2][1] = t1;
        bf[nf2 * 2 + 1][0] = t2;
        bf[nf2 * 2 + 1][1] = t3;
      }
#pragma unroll
      for (int mf = 0; mf < 4; mf++)
#pragma unroll
        for (int nf = 0; nf < 8; nf++) MMA16816(acc[mf][nf], af[mf], bf[nf]);
    }
  }

  // Epilogue: fused activation, direct float2 stores.
#pragma unroll
  for (int mf = 0; mf < 4; mf++) {
    const int r0 = mBase + warp_m + mf * 16 + (lid >> 2);
#pragma unroll
    for (int nf = 0; nf < 8; nf++) {
      const int cc = nBase + warp_n + nf * 8 + (lid & 3) * 2;
      float v[4] = {acc[mf][nf][0], acc[mf][nf][1], acc[mf][nf][2],
                    acc[mf][nf][3]};
      if (act == ACT_SIGMOID) {
#pragma unroll
        for (int q = 0; q < 4; q++) v[q] = 1.f / (1.f + expf(-v[q]));
      } else if (act == ACT_EWK) {
        const float2 w0 = *(const float2*)&aux[(size_t)r0 * kD + cc];
        const float2 w1 = *(const float2*)&aux[(size_t)(r0 + 8) * kD + cc];
        v[0] = expf(v[0] - expf(w0.x));
        v[1] = expf(v[1] - expf(w0.y));
        v[2] = expf(v[2] - expf(w1.x));
        v[3] = expf(v[3] - expf(w1.y));
      }
      *(float2*)&C[(size_t)r0 * kD + cc] = make_float2(v[0], v[1]);
      *(float2*)&C[(size_t)(r0 + 8) * kD + cc] = make_float2(v[2], v[3]);
    }
  }
}

// ------------------------------ fp32 -> fp16 -------------------------------
struct Ptr5 { const float* p[5]; };

__global__ __launch_bounds__(256) void cvt_f2h(const float* __restrict__ s,
                                               __half2* __restrict__ d, int n4) {
  int i = blockIdx.x * blockDim.x + threadIdx.x;
  const int stride = gridDim.x * blockDim.x;
  for (; i < n4; i += stride) {
    const float4 v = ((const float4*)s)[i];
    d[2 * i] = __floats2half2_rn(v.x, v.y);
    d[2 * i + 1] = __floats2half2_rn(v.z, v.w);
  }
}

__global__ __launch_bounds__(256) void cvt_w5(Ptr5 src, __half2* __restrict__ d) {
  const int n4 = kD * kD / 4;
  const float* s = src.p[blockIdx.z];
  __half2* dz = d + (size_t)blockIdx.z * (kD * kD / 2);
  int i = blockIdx.x * blockDim.x + threadIdx.x;
  const int stride = gridDim.x * blockDim.x;
  for (; i < n4; i += stride) {
    const float4 v = ((const float4*)s)[i];
    dz[2 * i] = __floats2half2_rn(v.x, v.y);
    dz[2 * i + 1] = __floats2half2_rn(v.z, v.w);
  }
}

// ------------------------------- scan kernels ------------------------------
__global__ __launch_bounds__(256) void scan_partial(const float* __restrict__ td) {
  const int e = blockIdx.x * 256 + threadIdx.x;
  const int b = blockIdx.y;
  const int c = blockIdx.z;
  const float dec = expf(td[e]);
  float num = 0.f, den = 0.f;
  int base = (b * kS + c * kCLen) * kD + e;
#pragma unroll 4
  for (int i = 0; i < kCLen; i++) {
    const float ew = g_ewk[base];
    const float vv = g_v[base];
    num = dec * num + ew * vv;
    den = dec * den + ew;
    base += kD;
  }
  const int ci = (c * kB + b) * kD + e;
  g_cnum[ci] = num;
  g_cden[ci] = den;
}

__global__ __launch_bounds__(256) void scan_carry(const float* __restrict__ td,
                                                  float* __restrict__ out) {
  const int e = blockIdx.x * 256 + threadIdx.x;
  const int b = blockIdx.y;
  const float decL = expf(td[e] * (float)kCLen);
  float num = 0.f, den = 0.f;
#pragma unroll 8
  for (int c = 0; c < kChunks; c++) {
    const int ci = (c * kB + b) * kD + e;
    g_inum[ci] = num;
    g_iden[ci] = den;
    num = decL * num + g_cnum[ci];
    den = decL * den + g_cden[ci];
  }
  float* fs = out + (size_t)kM * kD;
  fs[b * 2 * kD + e] = num;
  fs[b * 2 * kD + kD + e] = den;
}

// Rescan with carry-in; write y = r*wkv directly as fp16 (Wo GEMM rounds to
// fp16 anyway, so this adds zero error and kills the fp32 y write + cvt pass).
__global__ __launch_bounds__(256) void scan_final(const float* __restrict__ td) {
  const int e = blockIdx.x * 256 + threadIdx.x;
  const int b = blockIdx.y;
  const int c = blockIdx.z;
  const float dec = expf(td[e]);
  const int ci = (c * kB + b) * kD + e;
  float num = g_inum[ci];
  float den = g_iden[ci];
  int base = (b * kS + c * kCLen) * kD + e;
#pragma unroll 4
  for (int i = 0; i < kCLen; i++) {
    const float ew = g_ewk[base];
    const float vv = g_v[base];
    const float rr = g_r[base];
    num = dec * num + ew * vv;
    den = dec * den + ew;
    const float wkv = num / (den + 1e-8f);
    g_yh[base] = __float2half_rn(rr * wkv);
    base += kD;
  }
}

// ---------------------------------------------------------------------------
extern "C" void kernel_launch(void* const* d_in, const int* in_sizes, int n_in,
                              void* d_out, int out_size) {
  const float* x = (const float*)d_in[0];
  Ptr5 wp;
  for (int i = 0; i < 5; i++) wp.p[i] = (const float*)d_in[i + 1];
  const float* td = (const float*)d_in[6];
  float* out = (float*)d_out;

  float *pr, *pw, *pe, *pv;
  cudaGetSymbolAddress((void**)&pr, g_r);
  cudaGetSymbolAddress((void**)&pw, g_w);
  cudaGetSymbolAddress((void**)&pe, g_ewk);
  cudaGetSymbolAddress((void**)&pv, g_v);
  __half *xh, *yh, *wh;
  cudaGetSymbolAddress((void**)&xh, g_xh);
  cudaGetSymbolAddress((void**)&yh, g_yh);
  cudaGetSymbolAddress((void**)&wh, g_wh);

  cudaFuncSetAttribute(gemm_hmma, cudaFuncAttributeMaxDynamicSharedMemorySize,
                       SMEM_BYTES);

  cvt_f2h<<<4096, 256>>>(x, (__half2*)xh, kM * kD / 4);
  cvt_w5<<<dim3(1024, 1, 5), 256>>>(wp, (__half2*)wh);

  dim3 gg(kD / BN, kM / BM);  // (16, 128)
  const __half* Wr = wh + 0 * (size_t)kD * kD;
  const __half* Ww = wh + 1 * (size_t)kD * kD;
  const __half* Wk = wh + 2 * (size_t)kD * kD;
  const __half* Wv = wh + 3 * (size_t)kD * kD;
  const __half* Wo = wh + 4 * (size_t)kD * kD;

  gemm_hmma<<<gg, NTHR, SMEM_BYTES>>>(xh, Wr, pr, nullptr, ACT_SIGMOID);
  gemm_hmma<<<gg, NTHR, SMEM_BYTES>>>(xh, Ww, pw, nullptr, ACT_NONE);
  gemm_hmma<<<gg, NTHR, SMEM_BYTES>>>(xh, Wk, pe, pw, ACT_EWK);
  gemm_hmma<<<gg, NTHR, SMEM_BYTES>>>(xh, Wv, pv, nullptr, ACT_NONE);

  dim3 gs(kD / 256, kB, kChunks);
  scan_partial<<<gs, 256>>>(td);
  scan_carry<<<dim3(kD / 256, kB), 256>>>(td, out);
  scan_final<<<gs, 256>>>(td);

  gemm_hmma<<<gg, NTHR, SMEM_BYTES>>>(yh, Wo, out, nullptr, ACT_NONE);
}

// round 5
// speedup vs baseline: 8.1146x; 1.0649x over previous
#include <cuda_runtime.h>
#include <cuda_fp16.h>
#include <math.h>
#include <stdint.h>

// ---------------------------------------------------------------------------
// TimeMix (RWKV-style): B=4, S=4096, D=2048 — fp16 mma.sync, fused projections
// ---------------------------------------------------------------------------

namespace {
constexpr int kB = 4;
constexpr int kS = 4096;
constexpr int kD = 2048;
constexpr int kM = kB * kS;          // 16384
constexpr int kChunks = 64;
constexpr int kCLen = kS / kChunks;  // 64

constexpr int BM = 128, BN = 128, BKH = 64;  // BKH halves = 128 B rows
constexpr int NTHR = 128;                    // 4 warps, 2x2 of 64x64
constexpr int KSTAGES = kD / BKH;            // 32
constexpr uint32_t A_BYTES = BM * 128;       // 16384
constexpr uint32_t STAGE_BYTES = 2 * A_BYTES;       // 32768
constexpr uint32_t SMEM_BYTES = 3 * STAGE_BYTES;    // 98304
constexpr int NTILES = kD / BN;              // 16
}  // namespace

// Scratch (device globals; allocation APIs forbidden)
__device__ float g_r[kM * kD];
__device__ float g_w[kM * kD];
__device__ float g_k[kM * kD];
__device__ float g_v[kM * kD];
__device__ float g_cnum[kChunks * kB * kD];
__device__ float g_cden[kChunks * kB * kD];
__device__ float g_inum[kChunks * kB * kD];
__device__ float g_iden[kChunks * kB * kD];
__device__ __align__(16) __half g_xh[kM * kD];
__device__ __align__(16) __half g_yh[kM * kD];
__device__ __align__(16) __half g_wh[5][kD * kD];

enum { ACT_NONE = 0, ACT_SIGMOID = 1 };

// ------------------------------- asm helpers -------------------------------
__device__ __forceinline__ uint32_t smem_u32(const void* p) {
  uint32_t a;
  asm("{ .reg .u64 t; cvta.to.shared.u64 t, %1; cvt.u32.u64 %0, t; }"
      : "=r"(a) : "l"(p));
  return a;
}
__device__ __forceinline__ void cp16(uint32_t dst, const void* src) {
  asm volatile("cp.async.cg.shared.global [%0], [%1], 16;" :: "r"(dst), "l"(src));
}
#define CP_COMMIT() asm volatile("cp.async.commit_group;" ::: "memory")
#define CP_WAIT1() asm volatile("cp.async.wait_group 1;" ::: "memory")

#define LDM_X4(r0, r1, r2, r3, addr)                                           \
  asm volatile("ldmatrix.sync.aligned.m8n8.x4.shared.b16 {%0,%1,%2,%3}, [%4];" \
               : "=r"(r0), "=r"(r1), "=r"(r2), "=r"(r3) : "r"(addr))

#define MMA16816(d, a, b)                                                   \
  asm volatile(                                                             \
      "mma.sync.aligned.m16n8k16.row.col.f32.f16.f16.f32 "                  \
      "{%0,%1,%2,%3}, {%4,%5,%6,%7}, {%8,%9}, {%0,%1,%2,%3};"               \
      : "+f"(d[0]), "+f"(d[1]), "+f"(d[2]), "+f"(d[3])                      \
      : "r"(a[0]), "r"(a[1]), "r"(a[2]), "r"(a[3]), "r"(b[0]), "r"(b[1]))

__device__ __forceinline__ uint32_t swz(uint32_t off) {
  return off ^ ((off >> 3) & 0x70);
}

// Fill one stage: A tile 128 x 128B, B tile 128 x 128B. K-major, SW128.
__device__ __forceinline__ void stage_fill(uint32_t slotbase, const __half* A,
                                           const __half* W, int mBase,
                                           int nBase, int k0, int tid) {
#pragma unroll
  for (int t = 0; t < 16; t++) {
    const int idx = tid + t * NTHR;     // 0..2047
    const int row = (idx & 1023) >> 3;  // 0..127
    const int j = idx & 7;              // 16B chunk in row
    const __half* src;
    uint32_t dstBase;
    if (idx < 1024) {
      src = A + (size_t)(mBase + row) * kD;
      dstBase = slotbase;
    } else {
      src = W + (size_t)(nBase + row) * kD;
      dstBase = slotbase + A_BYTES;
    }
    const uint32_t off = (uint32_t)row * 128u + (uint32_t)j * 16u;
    cp16(dstBase + swz(off), src + k0 + j * 8);
  }
}

// ---------------------------------------------------------------------------
// GEMM core: C[m,n] = act( sum_k A[m,k] * W[n,k] ), fp16 in, fp32 accum.
// CTA 128x128, 4 warps 2(M)x2(N), 64x64 warp tiles, mma m16n8k16.
// ---------------------------------------------------------------------------
__device__ __forceinline__ void gemm_core(const __half* __restrict__ A,
                                          const __half* __restrict__ W,
                                          float* __restrict__ C, int act,
                                          int mBase, int nBase, uint32_t sb,
                                          int tid) {
  const int wid = tid >> 5;
  const int lid = tid & 31;
  const int warp_m = (wid & 1) * 64;
  const int warp_n = (wid >> 1) * 64;

  float acc[4][8][4];
#pragma unroll
  for (int a = 0; a < 4; a++)
#pragma unroll
    for (int b = 0; b < 8; b++)
#pragma unroll
      for (int c = 0; c < 4; c++) acc[a][b][c] = 0.f;

  stage_fill(sb, A, W, mBase, nBase, 0, tid);
  CP_COMMIT();
  stage_fill(sb + STAGE_BYTES, A, W, mBase, nBase, BKH, tid);
  CP_COMMIT();

  // ldmatrix lane geometry
  const int am = lid >> 3;
  const int a_row = ((am & 1) * 8) + (lid & 7);
  const int a_kb = (am >> 1) * 16;
  const int b_row = ((am >> 1) * 8) + (lid & 7);
  const int b_kb = (am & 1) * 16;

  uint32_t curSlot = sb, fillSlot = sb + 2 * STAGE_BYTES;
  for (int i = 0; i < KSTAGES; i++) {
    CP_WAIT1();
    __syncthreads();
    if (i + 2 < KSTAGES)
      stage_fill(fillSlot, A, W, mBase, nBase, (i + 2) * BKH, tid);
    CP_COMMIT();

    const uint32_t sA = curSlot;
    const uint32_t sB = curSlot + A_BYTES;
#pragma unroll
    for (int ks = 0; ks < 4; ks++) {
      uint32_t af[4][4];
#pragma unroll
      for (int mf = 0; mf < 4; mf++) {
        const uint32_t off =
            (uint32_t)(warp_m + mf * 16 + a_row) * 128u + ks * 32 + a_kb;
        LDM_X4(af[mf][0], af[mf][1], af[mf][2], af[mf][3], sA + swz(off));
      }
      uint32_t bf[8][2];
#pragma unroll
      for (int nf2 = 0; nf2 < 4; nf2++) {
        const uint32_t off =
            (uint32_t)(warp_n + nf2 * 16 + b_row) * 128u + ks * 32 + b_kb;
        uint32_t t0, t1, t2, t3;
        LDM_X4(t0, t1, t2, t3, sB + swz(off));
        bf[nf2 * 2][0] = t0;
        bf[nf2 * 2][1] = t1;
        bf[nf2 * 2 + 1][0] = t2;
        bf[nf2 * 2 + 1][1] = t3;
      }
#pragma unroll
      for (int mf = 0; mf < 4; mf++)
#pragma unroll
        for (int nf = 0; nf < 8; nf++) MMA16816(acc[mf][nf], af[mf], bf[nf]);
    }
    // rotate slots: cur <- next, fill <- old cur
    const uint32_t old = curSlot;
    curSlot = (curSlot == sb + 2 * STAGE_BYTES) ? sb : curSlot + STAGE_BYTES;
    fillSlot = old;
  }

  // Epilogue: fused activation, direct float2 stores.
#pragma unroll
  for (int mf = 0; mf < 4; mf++) {
    const int r0 = mBase + warp_m + mf * 16 + (lid >> 2);
#pragma unroll
    for (int nf = 0; nf < 8; nf++) {
      const int cc = nBase + warp_n + nf * 8 + (lid & 3) * 2;
      float v[4] = {acc[mf][nf][0], acc[mf][nf][1], acc[mf][nf][2],
                    acc[mf][nf][3]};
      if (act == ACT_SIGMOID) {
#pragma unroll
        for (int q = 0; q < 4; q++) v[q] = 1.f / (1.f + expf(-v[q]));
      }
      *(float2*)&C[(size_t)r0 * kD + cc] = make_float2(v[0], v[1]);
      *(float2*)&C[(size_t)(r0 + 8) * kD + cc] = make_float2(v[2], v[3]);
    }
  }
}

struct Proj4 {
  const __half* W[4];
  float* C[4];
};

// Fused 4-projection GEMM: blockIdx.x = widx * NTILES + ntile.
__global__ __launch_bounds__(NTHR, 2) void gemm_fused(
    const __half* __restrict__ A, Proj4 p) {
  extern __shared__ char smem[];
  const uint32_t sb = smem_u32(smem);
  const int widx = blockIdx.x / NTILES;
  const int nb = blockIdx.x - widx * NTILES;
  gemm_core(A, p.W[widx], p.C[widx], widx == 0 ? ACT_SIGMOID : ACT_NONE,
            blockIdx.y * BM, nb * BN, sb, threadIdx.x);
}

// Single GEMM (output projection).
__global__ __launch_bounds__(NTHR, 2) void gemm_one(
    const __half* __restrict__ A, const __half* __restrict__ W,
    float* __restrict__ C) {
  extern __shared__ char smem[];
  const uint32_t sb = smem_u32(smem);
  gemm_core(A, W, C, ACT_NONE, blockIdx.y * BM, blockIdx.x * BN, sb,
            threadIdx.x);
}

// ------------------------------ fp32 -> fp16 -------------------------------
struct Ptr5 { const float* p[5]; };

__global__ __launch_bounds__(256) void cvt_f2h(const float* __restrict__ s,
                                               __half2* __restrict__ d, int n4) {
  int i = blockIdx.x * blockDim.x + threadIdx.x;
  const int stride = gridDim.x * blockDim.x;
  for (; i < n4; i += stride) {
    const float4 v = ((const float4*)s)[i];
    d[2 * i] = __floats2half2_rn(v.x, v.y);
    d[2 * i + 1] = __floats2half2_rn(v.z, v.w);
  }
}

__global__ __launch_bounds__(256) void cvt_w5(Ptr5 src, __half2* __restrict__ d) {
  const int n4 = kD * kD / 4;
  const float* s = src.p[blockIdx.z];
  __half2* dz = d + (size_t)blockIdx.z * (kD * kD / 2);
  int i = blockIdx.x * blockDim.x + threadIdx.x;
  const int stride = gridDim.x * blockDim.x;
  for (; i < n4; i += stride) {
    const float4 v = ((const float4*)s)[i];
    dz[2 * i] = __floats2half2_rn(v.x, v.y);
    dz[2 * i + 1] = __floats2half2_rn(v.z, v.w);
  }
}

// ------------------------------- scan kernels ------------------------------
// ewk = exp(k - exp(w)) recomputed inline (identical in both passes).
__global__ __launch_bounds__(256) void scan_partial(const float* __restrict__ td) {
  const int e = blockIdx.x * 256 + threadIdx.x;
  const int b = blockIdx.y;
  const int c = blockIdx.z;
  const float dec = expf(td[e]);
  float num = 0.f, den = 0.f;
  int base = (b * kS + c * kCLen) * kD + e;
#pragma unroll 4
  for (int i = 0; i < kCLen; i++) {
    const float ew = expf(g_k[base] - expf(g_w[base]));
    const float vv = g_v[base];
    num = dec * num + ew * vv;
    den = dec * den + ew;
    base += kD;
  }
  const int ci = (c * kB + b) * kD + e;
  g_cnum[ci] = num;
  g_cden[ci] = den;
}

__global__ __launch_bounds__(256) void scan_carry(const float* __restrict__ td,
                                                  float* __restrict__ out) {
  const int e = blockIdx.x * 256 + threadIdx.x;
  const int b = blockIdx.y;
  const float decL = expf(td[e] * (float)kCLen);
  float num = 0.f, den = 0.f;
#pragma unroll 8
  for (int c = 0; c < kChunks; c++) {
    const int ci = (c * kB + b) * kD + e;
    g_inum[ci] = num;
    g_iden[ci] = den;
    num = decL * num + g_cnum[ci];
    den = decL * den + g_cden[ci];
  }
  float* fs = out + (size_t)kM * kD;
  fs[b * 2 * kD + e] = num;
  fs[b * 2 * kD + kD + e] = den;
}

// Rescan with carry-in; y = r*wkv written directly as fp16 (Wo GEMM rounds
// to fp16 anyway — zero extra error).
__global__ __launch_bounds__(256) void scan_final(const float* __restrict__ td) {
  const int e = blockIdx.x * 256 + threadIdx.x;
  const int b = blockIdx.y;
  const int c = blockIdx.z;
  const float dec = expf(td[e]);
  const int ci = (c * kB + b) * kD + e;
  float num = g_inum[ci];
  float den = g_iden[ci];
  int base = (b * kS + c * kCLen) * kD + e;
#pragma unroll 4
  for (int i = 0; i < kCLen; i++) {
    const float ew = expf(g_k[base] - expf(g_w[base]));
    const float vv = g_v[base];
    const float rr = g_r[base];
    num = dec * num + ew * vv;
    den = dec * den + ew;
    const float wkv = num / (den + 1e-8f);
    g_yh[base] = __float2half_rn(rr * wkv);
    base += kD;
  }
}

// ---------------------------------------------------------------------------
extern "C" void kernel_launch(void* const* d_in, const int* in_sizes, int n_in,
                              void* d_out, int out_size) {
  const float* x = (const float*)d_in[0];
  Ptr5 wp;
  for (int i = 0; i < 5; i++) wp.p[i] = (const float*)d_in[i + 1];
  const float* td = (const float*)d_in[6];
  float* out = (float*)d_out;

  float *pr, *pw, *pk, *pv;
  cudaGetSymbolAddress((void**)&pr, g_r);
  cudaGetSymbolAddress((void**)&pw, g_w);
  cudaGetSymbolAddress((void**)&pk, g_k);
  cudaGetSymbolAddress((void**)&pv, g_v);
  __half *xh, *yh, *wh;
  cudaGetSymbolAddress((void**)&xh, g_xh);
  cudaGetSymbolAddress((void**)&yh, g_yh);
  cudaGetSymbolAddress((void**)&wh, g_wh);

  cudaFuncSetAttribute(gemm_fused, cudaFuncAttributeMaxDynamicSharedMemorySize,
                       SMEM_BYTES);
  cudaFuncSetAttribute(gemm_one, cudaFuncAttributeMaxDynamicSharedMemorySize,
                       SMEM_BYTES);

  cvt_f2h<<<4096, 256>>>(x, (__half2*)xh, kM * kD / 4);
  cvt_w5<<<dim3(1024, 1, 5), 256>>>(wp, (__half2*)wh);

  Proj4 p;
  p.W[0] = wh + 0 * (size_t)kD * kD;  // Wr
  p.W[1] = wh + 1 * (size_t)kD * kD;  // Ww
  p.W[2] = wh + 2 * (size_t)kD * kD;  // Wk
  p.W[3] = wh + 3 * (size_t)kD * kD;  // Wv
  p.C[0] = pr; p.C[1] = pw; p.C[2] = pk; p.C[3] = pv;
  const __half* Wo = wh + 4 * (size_t)kD * kD;

  gemm_fused<<<dim3(4 * NTILES, kM / BM), NTHR, SMEM_BYTES>>>(xh, p);

  dim3 gs(kD / 256, kB, kChunks);
  scan_partial<<<gs, 256>>>(td);
  scan_carry<<<dim3(kD / 256, kB), 256>>>(td, out);
  scan_final<<<gs, 256>>>(td);

  gemm_one<<<dim3(NTILES, kM / BM), NTHR, SMEM_BYTES>>>(yh, Wo, out);
}

// round 6
// speedup vs baseline: 8.1317x; 1.0021x over previous
#include <cuda_runtime.h>
#include <cuda_fp16.h>
#include <math.h>
#include <stdint.h>

// ---------------------------------------------------------------------------
// TimeMix (RWKV-style): B=4, S=4096, D=2048 — fp16 mma.sync, fused projections,
// fp16 r/v scan operands, double-buffered fragments.
// ---------------------------------------------------------------------------

namespace {
constexpr int kB = 4;
constexpr int kS = 4096;
constexpr int kD = 2048;
constexpr int kM = kB * kS;          // 16384
constexpr int kChunks = 64;
constexpr int kCLen = kS / kChunks;  // 64

constexpr int BM = 128, BN = 128, BKH = 64;  // BKH halves = 128 B rows
constexpr int NTHR = 128;                    // 4 warps, 2x2 of 64x64
constexpr int KSTAGES = kD / BKH;            // 32
constexpr uint32_t A_BYTES = BM * 128;       // 16384
constexpr uint32_t STAGE_BYTES = 2 * A_BYTES;     // 32768
constexpr uint32_t SMEM_BYTES = 3 * STAGE_BYTES;  // 98304
constexpr int NTILES = kD / BN;              // 16
}  // namespace

// Scratch (device globals; allocation APIs forbidden)
__device__ float g_w[kM * kD];
__device__ float g_k[kM * kD];
__device__ __align__(16) __half g_rh[kM * kD];
__device__ __align__(16) __half g_vh[kM * kD];
__device__ float g_cnum[kChunks * kB * kD];
__device__ float g_cden[kChunks * kB * kD];
__device__ float g_inum[kChunks * kB * kD];
__device__ float g_iden[kChunks * kB * kD];
__device__ __align__(16) __half g_xh[kM * kD];
__device__ __align__(16) __half g_yh[kM * kD];
__device__ __align__(16) __half g_wh[5][kD * kD];

// ------------------------------- asm helpers -------------------------------
__device__ __forceinline__ uint32_t smem_u32(const void* p) {
  uint32_t a;
  asm("{ .reg .u64 t; cvta.to.shared.u64 t, %1; cvt.u32.u64 %0, t; }"
      : "=r"(a) : "l"(p));
  return a;
}
__device__ __forceinline__ void cp16(uint32_t dst, const void* src) {
  asm volatile("cp.async.cg.shared.global [%0], [%1], 16;" :: "r"(dst), "l"(src));
}
#define CP_COMMIT() asm volatile("cp.async.commit_group;" ::: "memory")
#define CP_WAIT1() asm volatile("cp.async.wait_group 1;" ::: "memory")

#define LDM_X4(r0, r1, r2, r3, addr)                                           \
  asm volatile("ldmatrix.sync.aligned.m8n8.x4.shared.b16 {%0,%1,%2,%3}, [%4];" \
               : "=r"(r0), "=r"(r1), "=r"(r2), "=r"(r3) : "r"(addr))

#define MMA16816(d, a, b)                                                   \
  asm volatile(                                                             \
      "mma.sync.aligned.m16n8k16.row.col.f32.f16.f16.f32 "                  \
      "{%0,%1,%2,%3}, {%4,%5,%6,%7}, {%8,%9}, {%0,%1,%2,%3};"               \
      : "+f"(d[0]), "+f"(d[1]), "+f"(d[2]), "+f"(d[3])                      \
      : "r"(a[0]), "r"(a[1]), "r"(a[2]), "r"(b[0]), "r"(b[1]))

// NOTE: macro above must pass all 4 a regs; fixed below.
#undef MMA16816
#define MMA16816(d, a, b)                                                   \
  asm volatile(                                                             \
      "mma.sync.aligned.m16n8k16.row.col.f32.f16.f16.f32 "                  \
      "{%0,%1,%2,%3}, {%4,%5,%6,%7}, {%8,%9}, {%0,%1,%2,%3};"               \
      : "+f"(d[0]), "+f"(d[1]), "+f"(d[2]), "+f"(d[3])                      \
      : "r"(a[0]), "r"(a[1]), "r"(a[2]), "r"(a[3]), "r"(b[0]), "r"(b[1]))

__device__ __forceinline__ uint32_t swz(uint32_t off) {
  return off ^ ((off >> 3) & 0x70);
}

// Fill one stage: A tile 128 x 128B, B tile 128 x 128B. K-major, SW128.
__device__ __forceinline__ void stage_fill(uint32_t slotbase, const __half* A,
                                           const __half* W, int mBase,
                                           int nBase, int k0, int tid) {
#pragma unroll
  for (int t = 0; t < 16; t++) {
    const int idx = tid + t * NTHR;     // 0..2047
    const int row = (idx & 1023) >> 3;  // 0..127
    const int j = idx & 7;              // 16B chunk in row
    const __half* src;
    uint32_t dstBase;
    if (idx < 1024) {
      src = A + (size_t)(mBase + row) * kD;
      dstBase = slotbase;
    } else {
      src = W + (size_t)(nBase + row) * kD;
      dstBase = slotbase + A_BYTES;
    }
    const uint32_t off = (uint32_t)row * 128u + (uint32_t)j * 16u;
    cp16(dstBase + swz(off), src + k0 + j * 8);
  }
}

// Load one ks-slice of fragments.
__device__ __forceinline__ void load_frags(uint32_t sA, uint32_t sB, int ks,
                                           int warp_m, int warp_n, int a_row,
                                           int a_kb, int b_row, int b_kb,
                                           uint32_t af[4][4], uint32_t bf[8][2]) {
#pragma unroll
  for (int mf = 0; mf < 4; mf++) {
    const uint32_t off =
        (uint32_t)(warp_m + mf * 16 + a_row) * 128u + ks * 32 + a_kb;
    LDM_X4(af[mf][0], af[mf][1], af[mf][2], af[mf][3], sA + swz(off));
  }
#pragma unroll
  for (int nf2 = 0; nf2 < 4; nf2++) {
    const uint32_t off =
        (uint32_t)(warp_n + nf2 * 16 + b_row) * 128u + ks * 32 + b_kb;
    uint32_t t0, t1, t2, t3;
    LDM_X4(t0, t1, t2, t3, sB + swz(off));
    bf[nf2 * 2][0] = t0;
    bf[nf2 * 2][1] = t1;
    bf[nf2 * 2 + 1][0] = t2;
    bf[nf2 * 2 + 1][1] = t3;
  }
}

// ---------------------------------------------------------------------------
// GEMM core: C[m,n] = act( sum_k A[m,k] * W[n,k] ), fp16 in, fp32 accum.
// outMode: 0 = float store, 1 = sigmoid + half store, 2 = half store.
// ---------------------------------------------------------------------------
__device__ __forceinline__ void gemm_core(const __half* __restrict__ A,
                                          const __half* __restrict__ W,
                                          void* __restrict__ C, int outMode,
                                          int mBase, int nBase, uint32_t sb,
                                          int tid) {
  const int wid = tid >> 5;
  const int lid = tid & 31;
  const int warp_m = (wid & 1) * 64;
  const int warp_n = (wid >> 1) * 64;

  float acc[4][8][4];
#pragma unroll
  for (int a = 0; a < 4; a++)
#pragma unroll
    for (int b = 0; b < 8; b++)
#pragma unroll
      for (int c = 0; c < 4; c++) acc[a][b][c] = 0.f;

  stage_fill(sb, A, W, mBase, nBase, 0, tid);
  CP_COMMIT();
  stage_fill(sb + STAGE_BYTES, A, W, mBase, nBase, BKH, tid);
  CP_COMMIT();

  const int am = lid >> 3;
  const int a_row = ((am & 1) * 8) + (lid & 7);
  const int a_kb = (am >> 1) * 16;
  const int b_row = ((am >> 1) * 8) + (lid & 7);
  const int b_kb = (am & 1) * 16;

  uint32_t af[2][4][4];
  uint32_t bf[2][8][2];

  uint32_t curSlot = sb, fillSlot = sb + 2 * STAGE_BYTES;
  for (int i = 0; i < KSTAGES; i++) {
    CP_WAIT1();
    __syncthreads();
    if (i + 2 < KSTAGES)
      stage_fill(fillSlot, A, W, mBase, nBase, (i + 2) * BKH, tid);
    CP_COMMIT();

    const uint32_t sA = curSlot;
    const uint32_t sB = curSlot + A_BYTES;

    load_frags(sA, sB, 0, warp_m, warp_n, a_row, a_kb, b_row, b_kb, af[0],
               bf[0]);
#pragma unroll
    for (int ks = 0; ks < 4; ks++) {
      const int p = ks & 1;
      if (ks < 3)
        load_frags(sA, sB, ks + 1, warp_m, warp_n, a_row, a_kb, b_row, b_kb,
                   af[1 - p], bf[1 - p]);
#pragma unroll
      for (int mf = 0; mf < 4; mf++)
#pragma unroll
        for (int nf = 0; nf < 8; nf++)
          MMA16816(acc[mf][nf], af[p][mf], bf[p][nf]);
    }
    const uint32_t old = curSlot;
    curSlot = (curSlot == sb + 2 * STAGE_BYTES) ? sb : curSlot + STAGE_BYTES;
    fillSlot = old;
  }

  // Epilogue.
#pragma unroll
  for (int mf = 0; mf < 4; mf++) {
    const int r0 = mBase + warp_m + mf * 16 + (lid >> 2);
#pragma unroll
    for (int nf = 0; nf < 8; nf++) {
      const int cc = nBase + warp_n + nf * 8 + (lid & 3) * 2;
      float v[4] = {acc[mf][nf][0], acc[mf][nf][1], acc[mf][nf][2],
                    acc[mf][nf][3]};
      if (outMode == 1) {
#pragma unroll
        for (int q = 0; q < 4; q++) v[q] = 1.f / (1.f + expf(-v[q]));
      }
      if (outMode == 0) {
        float* Cf = (float*)C;
        *(float2*)&Cf[(size_t)r0 * kD + cc] = make_float2(v[0], v[1]);
        *(float2*)&Cf[(size_t)(r0 + 8) * kD + cc] = make_float2(v[2], v[3]);
      } else {
        __half* Ch = (__half*)C;
        *(__half2*)&Ch[(size_t)r0 * kD + cc] = __floats2half2_rn(v[0], v[1]);
        *(__half2*)&Ch[(size_t)(r0 + 8) * kD + cc] =
            __floats2half2_rn(v[2], v[3]);
      }
    }
  }
}

struct Proj4 {
  const __half* W[4];
  void* C[4];
};

// Fused 4-projection GEMM: widx 0=r(sigmoid,half) 1=w(f32) 2=k(f32) 3=v(half)
__global__ __launch_bounds__(NTHR, 2) void gemm_fused(
    const __half* __restrict__ A, Proj4 p) {
  extern __shared__ char smem[];
  const uint32_t sb = smem_u32(smem);
  const int widx = blockIdx.x / NTILES;
  const int nb = blockIdx.x - widx * NTILES;
  const int mode = (widx == 0) ? 1 : (widx == 3 ? 2 : 0);
  gemm_core(A, p.W[widx], p.C[widx], mode, blockIdx.y * BM, nb * BN, sb,
            threadIdx.x);
}

// Output projection (float out).
__global__ __launch_bounds__(NTHR, 2) void gemm_one(
    const __half* __restrict__ A, const __half* __restrict__ W,
    float* __restrict__ C) {
  extern __shared__ char smem[];
  const uint32_t sb = smem_u32(smem);
  gemm_core(A, W, C, 0, blockIdx.y * BM, blockIdx.x * BN, sb, threadIdx.x);
}

// ---------------------- fp32 -> fp16 (x + 5 weights) -----------------------
struct Ptr5 { const float* p[5]; };

__global__ __launch_bounds__(256) void cvt_all(const float* __restrict__ x,
                                               Ptr5 wsrc,
                                               __half2* __restrict__ xh,
                                               __half2* __restrict__ wh) {
  const int z = blockIdx.z;
  const float* s;
  __half2* d;
  int n4;
  if (z == 0) {
    s = x; d = xh; n4 = kM * kD / 4;
  } else {
    s = wsrc.p[z - 1];
    d = wh + (size_t)(z - 1) * (kD * kD / 2);
    n4 = kD * kD / 4;
  }
  int i = blockIdx.x * blockDim.x + threadIdx.x;
  const int stride = gridDim.x * blockDim.x;
  for (; i < n4; i += stride) {
    const float4 v = ((const float4*)s)[i];
    d[2 * i] = __floats2half2_rn(v.x, v.y);
    d[2 * i + 1] = __floats2half2_rn(v.z, v.w);
  }
}

// ------------------------------- scan kernels ------------------------------
__global__ __launch_bounds__(256) void scan_partial(const float* __restrict__ td) {
  const int e = blockIdx.x * 256 + threadIdx.x;
  const int b = blockIdx.y;
  const int c = blockIdx.z;
  const float dec = expf(td[e]);
  float num = 0.f, den = 0.f;
  int base = (b * kS + c * kCLen) * kD + e;
#pragma unroll 4
  for (int i = 0; i < kCLen; i++) {
    const float ew = expf(g_k[base] - expf(g_w[base]));
    const float vv = __half2float(g_vh[base]);
    num = dec * num + ew * vv;
    den = dec * den + ew;
    base += kD;
  }
  const int ci = (c * kB + b) * kD + e;
  g_cnum[ci] = num;
  g_cden[ci] = den;
}

__global__ __launch_bounds__(256) void scan_carry(const float* __restrict__ td,
                                                  float* __restrict__ out) {
  const int e = blockIdx.x * 256 + threadIdx.x;
  const int b = blockIdx.y;
  const float decL = expf(td[e] * (float)kCLen);
  float num = 0.f, den = 0.f;
#pragma unroll 8
  for (int c = 0; c < kChunks; c++) {
    const int ci = (c * kB + b) * kD + e;
    g_inum[ci] = num;
    g_iden[ci] = den;
    num = decL * num + g_cnum[ci];
    den = decL * den + g_cden[ci];
  }
  float* fs = out + (size_t)kM * kD;
  fs[b * 2 * kD + e] = num;
  fs[b * 2 * kD + kD + e] = den;
}

__global__ __launch_bounds__(256) void scan_final(const float* __restrict__ td) {
  const int e = blockIdx.x * 256 + threadIdx.x;
  const int b = blockIdx.y;
  const int c = blockIdx.z;
  const float dec = expf(td[e]);
  const int ci = (c * kB + b) * kD + e;
  float num = g_inum[ci];
  float den = g_iden[ci];
  int base = (b * kS + c * kCLen) * kD + e;
#pragma unroll 4
  for (int i = 0; i < kCLen; i++) {
    const float ew = expf(g_k[base] - expf(g_w[base]));
    const float vv = __half2float(g_vh[base]);
    const float rr = __half2float(g_rh[base]);
    num = dec * num + ew * vv;
    den = dec * den + ew;
    const float wkv = num / (den + 1e-8f);
    g_yh[base] = __float2half_rn(rr * wkv);
    base += kD;
  }
}

// ---------------------------------------------------------------------------
extern "C" void kernel_launch(void* const* d_in, const int* in_sizes, int n_in,
                              void* d_out, int out_size) {
  const float* x = (const float*)d_in[0];
  Ptr5 wp;
  for (int i = 0; i < 5; i++) wp.p[i] = (const float*)d_in[i + 1];
  const float* td = (const float*)d_in[6];
  float* out = (float*)d_out;

  float *pw, *pk;
  cudaGetSymbolAddress((void**)&pw, g_w);
  cudaGetSymbolAddress((void**)&pk, g_k);
  __half *prh, *pvh, *xh, *yh, *wh;
  cudaGetSymbolAddress((void**)&prh, g_rh);
  cudaGetSymbolAddress((void**)&pvh, g_vh);
  cudaGetSymbolAddress((void**)&xh, g_xh);
  cudaGetSymbolAddress((void**)&yh, g_yh);
  cudaGetSymbolAddress((void**)&wh, g_wh);

  cudaFuncSetAttribute(gemm_fused, cudaFuncAttributeMaxDynamicSharedMemorySize,
                       SMEM_BYTES);
  cudaFuncSetAttribute(gemm_one, cudaFuncAttributeMaxDynamicSharedMemorySize,
                       SMEM_BYTES);

  cvt_all<<<dim3(2048, 1, 6), 256>>>(x, wp, (__half2*)xh, (__half2*)wh);

  Proj4 p;
  p.W[0] = wh + 0 * (size_t)kD * kD;  // Wr
  p.W[1] = wh + 1 * (size_t)kD * kD;  // Ww
  p.W[2] = wh + 2 * (size_t)kD * kD;  // Wk
  p.W[3] = wh + 3 * (size_t)kD * kD;  // Wv
  p.C[0] = prh; p.C[1] = pw; p.C[2] = pk; p.C[3] = pvh;
  const __half* Wo = wh + 4 * (size_t)kD * kD;

  gemm_fused<<<dim3(4 * NTILES, kM / BM), NTHR, SMEM_BYTES>>>(xh, p);

  dim3 gs(kD / 256, kB, kChunks);
  scan_partial<<<gs, 256>>>(td);
  scan_carry<<<dim3(kD / 256, kB), 256>>>(td, out);
  scan_final<<<gs, 256>>>(td);

  gemm_one<<<dim3(NTILES, kM / BM), NTHR, SMEM_BYTES>>>(yh, Wo, out);
}

// round 8
// speedup vs baseline: 8.4488x; 1.0390x over previous
#include <cuda_runtime.h>
#include <cuda_fp16.h>
#include <math.h>
#include <stdint.h>

// ---------------------------------------------------------------------------
// TimeMix (RWKV-style): B=4, S=4096, D=2048 — fp16 mma.sync, fused projections,
// warp-parallel carry scan (grid fixed), vectorized streaming scans.
// ---------------------------------------------------------------------------

namespace {
constexpr int kB = 4;
constexpr int kS = 4096;
constexpr int kD = 2048;
constexpr int kM = kB * kS;          // 16384
constexpr int kChunks = 64;
constexpr int kCLen = kS / kChunks;  // 64

constexpr int BM = 128, BN = 128, BKH = 64;  // BKH halves = 128 B rows
constexpr int NTHR = 128;                    // 4 warps, 2x2 of 64x64
constexpr int KSTAGES = kD / BKH;            // 32
constexpr uint32_t A_BYTES = BM * 128;       // 16384
constexpr uint32_t STAGE_BYTES = 2 * A_BYTES;     // 32768
constexpr uint32_t SMEM_BYTES = 3 * STAGE_BYTES;  // 98304
constexpr int NTILES = kD / BN;              // 16
}  // namespace

// Scratch (device globals; allocation APIs forbidden)
__device__ float g_w[kM * kD];
__device__ float g_k[kM * kD];
__device__ __align__(16) __half g_rh[kM * kD];
__device__ __align__(16) __half g_vh[kM * kD];
__device__ float g_cnum[kChunks * kB * kD];
__device__ float g_cden[kChunks * kB * kD];
__device__ float g_inum[kChunks * kB * kD];
__device__ float g_iden[kChunks * kB * kD];
__device__ __align__(16) __half g_xh[kM * kD];
__device__ __align__(16) __half g_yh[kM * kD];
__device__ __align__(16) __half g_wh[5][kD * kD];

// ------------------------------- asm helpers -------------------------------
__device__ __forceinline__ uint32_t smem_u32(const void* p) {
  uint32_t a;
  asm("{ .reg .u64 t; cvta.to.shared.u64 t, %1; cvt.u32.u64 %0, t; }"
      : "=r"(a) : "l"(p));
  return a;
}
__device__ __forceinline__ void cp16(uint32_t dst, const void* src) {
  asm volatile("cp.async.cg.shared.global [%0], [%1], 16;" :: "r"(dst), "l"(src));
}
#define CP_COMMIT() asm volatile("cp.async.commit_group;" ::: "memory")
#define CP_WAIT1() asm volatile("cp.async.wait_group 1;" ::: "memory")

#define LDM_X4(r0, r1, r2, r3, addr)                                           \
  asm volatile("ldmatrix.sync.aligned.m8n8.x4.shared.b16 {%0,%1,%2,%3}, [%4];" \
               : "=r"(r0), "=r"(r1), "=r"(r2), "=r"(r3) : "r"(addr))

#define MMA16816(d, a, b)                                                   \
  asm volatile(                                                             \
      "mma.sync.aligned.m16n8k16.row.col.f32.f16.f16.f32 "                  \
      "{%0,%1,%2,%3}, {%4,%5,%6,%7}, {%8,%9}, {%0,%1,%2,%3};"               \
      : "+f"(d[0]), "+f"(d[1]), "+f"(d[2]), "+f"(d[3])                      \
      : "r"(a[0]), "r"(a[1]), "r"(a[2]), "r"(a[3]), "r"(b[0]), "r"(b[1]))

__device__ __forceinline__ uint32_t swz(uint32_t off) {
  return off ^ ((off >> 3) & 0x70);
}

// Fill one stage: A tile 128 x 128B, B tile 128 x 128B. K-major, SW128.
__device__ __forceinline__ void stage_fill(uint32_t slotbase, const __half* A,
                                           const __half* W, int mBase,
                                           int nBase, int k0, int tid) {
#pragma unroll
  for (int t = 0; t < 16; t++) {
    const int idx = tid + t * NTHR;     // 0..2047
    const int row = (idx & 1023) >> 3;  // 0..127
    const int j = idx & 7;              // 16B chunk in row
    const __half* src;
    uint32_t dstBase;
    if (idx < 1024) {
      src = A + (size_t)(mBase + row) * kD;
      dstBase = slotbase;
    } else {
      src = W + (size_t)(nBase + row) * kD;
      dstBase = slotbase + A_BYTES;
    }
    const uint32_t off = (uint32_t)row * 128u + (uint32_t)j * 16u;
    cp16(dstBase + swz(off), src + k0 + j * 8);
  }
}

// Load one ks-slice of fragments.
__device__ __forceinline__ void load_frags(uint32_t sA, uint32_t sB, int ks,
                                           int warp_m, int warp_n, int a_row,
                                           int a_kb, int b_row, int b_kb,
                                           uint32_t af[4][4], uint32_t bf[8][2]) {
#pragma unroll
  for (int mf = 0; mf < 4; mf++) {
    const uint32_t off =
        (uint32_t)(warp_m + mf * 16 + a_row) * 128u + ks * 32 + a_kb;
    LDM_X4(af[mf][0], af[mf][1], af[mf][2], af[mf][3], sA + swz(off));
  }
#pragma unroll
  for (int nf2 = 0; nf2 < 4; nf2++) {
    const uint32_t off =
        (uint32_t)(warp_n + nf2 * 16 + b_row) * 128u + ks * 32 + b_kb;
    uint32_t t0, t1, t2, t3;
    LDM_X4(t0, t1, t2, t3, sB + swz(off));
    bf[nf2 * 2][0] = t0;
    bf[nf2 * 2][1] = t1;
    bf[nf2 * 2 + 1][0] = t2;
    bf[nf2 * 2 + 1][1] = t3;
  }
}

// ---------------------------------------------------------------------------
// GEMM core: C[m,n] = act( sum_k A[m,k] * W[n,k] ), fp16 in, fp32 accum.
// outMode: 0 = float store, 1 = sigmoid + half store, 2 = half store.
// ---------------------------------------------------------------------------
__device__ __forceinline__ void gemm_core(const __half* __restrict__ A,
                                          const __half* __restrict__ W,
                                          void* __restrict__ C, int outMode,
                                          int mBase, int nBase, uint32_t sb,
                                          int tid) {
  const int wid = tid >> 5;
  const int lid = tid & 31;
  const int warp_m = (wid & 1) * 64;
  const int warp_n = (wid >> 1) * 64;

  float acc[4][8][4];
#pragma unroll
  for (int a = 0; a < 4; a++)
#pragma unroll
    for (int b = 0; b < 8; b++)
#pragma unroll
      for (int c = 0; c < 4; c++) acc[a][b][c] = 0.f;

  stage_fill(sb, A, W, mBase, nBase, 0, tid);
  CP_COMMIT();
  stage_fill(sb + STAGE_BYTES, A, W, mBase, nBase, BKH, tid);
  CP_COMMIT();

  const int am = lid >> 3;
  const int a_row = ((am & 1) * 8) + (lid & 7);
  const int a_kb = (am >> 1) * 16;
  const int b_row = ((am >> 1) * 8) + (lid & 7);
  const int b_kb = (am & 1) * 16;

  uint32_t af[2][4][4];
  uint32_t bf[2][8][2];

  uint32_t curSlot = sb, fillSlot = sb + 2 * STAGE_BYTES;
  for (int i = 0; i < KSTAGES; i++) {
    CP_WAIT1();
    __syncthreads();
    if (i + 2 < KSTAGES)
      stage_fill(fillSlot, A, W, mBase, nBase, (i + 2) * BKH, tid);
    CP_COMMIT();

    const uint32_t sA = curSlot;
    const uint32_t sB = curSlot + A_BYTES;

    load_frags(sA, sB, 0, warp_m, warp_n, a_row, a_kb, b_row, b_kb, af[0],
               bf[0]);
#pragma unroll
    for (int ks = 0; ks < 4; ks++) {
      const int p = ks & 1;
      if (ks < 3)
        load_frags(sA, sB, ks + 1, warp_m, warp_n, a_row, a_kb, b_row, b_kb,
                   af[1 - p], bf[1 - p]);
#pragma unroll
      for (int mf = 0; mf < 4; mf++)
#pragma unroll
        for (int nf = 0; nf < 8; nf++)
          MMA16816(acc[mf][nf], af[p][mf], bf[p][nf]);
    }
    const uint32_t old = curSlot;
    curSlot = (curSlot == sb + 2 * STAGE_BYTES) ? sb : curSlot + STAGE_BYTES;
    fillSlot = old;
  }

  // Epilogue.
#pragma unroll
  for (int mf = 0; mf < 4; mf++) {
    const int r0 = mBase + warp_m + mf * 16 + (lid >> 2);
#pragma unroll
    for (int nf = 0; nf < 8; nf++) {
      const int cc = nBase + warp_n + nf * 8 + (lid & 3) * 2;
      float v[4] = {acc[mf][nf][0], acc[mf][nf][1], acc[mf][nf][2],
                    acc[mf][nf][3]};
      if (outMode == 1) {
#pragma unroll
        for (int q = 0; q < 4; q++) v[q] = 1.f / (1.f + expf(-v[q]));
      }
      if (outMode == 0) {
        float* Cf = (float*)C;
        *(float2*)&Cf[(size_t)r0 * kD + cc] = make_float2(v[0], v[1]);
        *(float2*)&Cf[(size_t)(r0 + 8) * kD + cc] = make_float2(v[2], v[3]);
      } else {
        __half* Ch = (__half*)C;
        *(__half2*)&Ch[(size_t)r0 * kD + cc] = __floats2half2_rn(v[0], v[1]);
        *(__half2*)&Ch[(size_t)(r0 + 8) * kD + cc] =
            __floats2half2_rn(v[2], v[3]);
      }
    }
  }
}

struct Proj4 {
  const __half* W[4];
  void* C[4];
};

// Fused 4-projection GEMM: widx 0=r(sigmoid,half) 1=w(f32) 2=k(f32) 3=v(half)
__global__ __launch_bounds__(NTHR, 2) void gemm_fused(
    const __half* __restrict__ A, Proj4 p) {
  extern __shared__ char smem[];
  const uint32_t sb = smem_u32(smem);
  const int widx = blockIdx.x / NTILES;
  const int nb = blockIdx.x - widx * NTILES;
  const int mode = (widx == 0) ? 1 : (widx == 3 ? 2 : 0);
  gemm_core(A, p.W[widx], p.C[widx], mode, blockIdx.y * BM, nb * BN, sb,
            threadIdx.x);
}

// Output projection (float out).
__global__ __launch_bounds__(NTHR, 2) void gemm_one(
    const __half* __restrict__ A, const __half* __restrict__ W,
    float* __restrict__ C) {
  extern __shared__ char smem[];
  const uint32_t sb = smem_u32(smem);
  gemm_core(A, W, C, 0, blockIdx.y * BM, blockIdx.x * BN, sb, threadIdx.x);
}

// ---------------------- fp32 -> fp16 (x + 5 weights) -----------------------
struct Ptr5 { const float* p[5]; };

__global__ __launch_bounds__(256) void cvt_all(const float* __restrict__ x,
                                               Ptr5 wsrc,
                                               __half2* __restrict__ xh,
                                               __half2* __restrict__ wh) {
  const int z = blockIdx.z;
  const float* s;
  __half2* d;
  int n4;
  if (z == 0) {
    s = x; d = xh; n4 = kM * kD / 4;
  } else {
    s = wsrc.p[z - 1];
    d = wh + (size_t)(z - 1) * (kD * kD / 2);
    n4 = kD * kD / 4;
  }
  int i = blockIdx.x * blockDim.x + threadIdx.x;
  const int stride = gridDim.x * blockDim.x;
  for (; i < n4; i += stride) {
    const float4 v = ((const float4*)s)[i];
    d[2 * i] = __floats2half2_rn(v.x, v.y);
    d[2 * i + 1] = __floats2half2_rn(v.z, v.w);
  }
}

// ------------------------------- scan kernels ------------------------------
// Pass A: per-chunk local scan, 2 channels per thread, streaming loads.
__global__ __launch_bounds__(256) void scan_partial(const float* __restrict__ td) {
  const int e = (blockIdx.x * 256 + threadIdx.x) * 2;
  const int b = blockIdx.y;
  const int c = blockIdx.z;
  const float dec0 = expf(td[e]);
  const float dec1 = expf(td[e + 1]);
  float n0 = 0.f, n1 = 0.f, d0 = 0.f, d1 = 0.f;
  size_t base = (size_t)(b * kS + c * kCLen) * kD + e;
#pragma unroll 4
  for (int i = 0; i < kCLen; i++) {
    const float2 kk = __ldcs((const float2*)&g_k[base]);
    const float2 ww = __ldcs((const float2*)&g_w[base]);
    const __half2 vh = __ldcs((const __half2*)&g_vh[base]);
    const float2 vf = __half22float2(vh);
    const float ew0 = expf(kk.x - expf(ww.x));
    const float ew1 = expf(kk.y - expf(ww.y));
    n0 = fmaf(dec0, n0, ew0 * vf.x);
    n1 = fmaf(dec1, n1, ew1 * vf.y);
    d0 = fmaf(dec0, d0, ew0);
    d1 = fmaf(dec1, d1, ew1);
    base += kD;
  }
  const size_t ci = (size_t)(c * kB + b) * kD + e;
  *(float2*)&g_cnum[ci] = make_float2(n0, n1);
  *(float2*)&g_cden[ci] = make_float2(d0, d1);
}

// Pass B: cross-chunk carry via warp Kogge-Stone. ONE WARP PER (b,e) CHANNEL
// (kB*kD = 8192 warps total). Also emits final_state.
__global__ __launch_bounds__(256) void scan_carry(const float* __restrict__ td,
                                                  float* __restrict__ out) {
  const int gw = (blockIdx.x * 256 + threadIdx.x) >> 5;  // 0..8191
  const int lane = threadIdx.x & 31;
  const int b = gw >> 11;          // gw / kD
  const int e = gw & (kD - 1);     // gw % kD
  const float decL = expf(td[e] * (float)kCLen);

  // lane handles chunks 2*lane, 2*lane+1
  const int c0 = 2 * lane;
  const size_t ci0 = (size_t)(c0 * kB + b) * kD + e;
  const size_t ci1 = (size_t)((c0 + 1) * kB + b) * kD + e;
  const float pn0 = g_cnum[ci0], pd0 = g_cden[ci0];
  const float pn1 = g_cnum[ci1], pd1 = g_cden[ci1];

  // inclusive over this lane's pair (pair coefficient a = decL^2)
  float vn = fmaf(decL, pn0, pn1);
  float vd = fmaf(decL, pd0, pd1);

  float coef = decL * decL;
#pragma unroll
  for (int off = 1; off < 32; off <<= 1) {
    const float un = __shfl_up_sync(0xffffffffu, vn, off);
    const float ud = __shfl_up_sync(0xffffffffu, vd, off);
    if (lane >= off) {
      vn = fmaf(coef, un, vn);
      vd = fmaf(coef, ud, vd);
    }
    coef *= coef;
  }
  // exclusive carry into chunk 2*lane
  float en = __shfl_up_sync(0xffffffffu, vn, 1);
  float ed = __shfl_up_sync(0xffffffffu, vd, 1);
  if (lane == 0) { en = 0.f; ed = 0.f; }
  g_inum[ci0] = en;
  g_iden[ci0] = ed;
  g_inum[ci1] = fmaf(decL, en, pn0);
  g_iden[ci1] = fmaf(decL, ed, pd0);

  if (lane == 31) {  // final state after chunk 63
    float* fs = out + (size_t)kM * kD;
    fs[b * 2 * kD + e] = vn;
    fs[b * 2 * kD + kD + e] = vd;
  }
}

// Pass C: rescan with carry-in, y = r*wkv as fp16. 2 channels per thread.
__global__ __launch_bounds__(256) void scan_final(const float* __restrict__ td) {
  const int e = (blockIdx.x * 256 + threadIdx.x) * 2;
  const int b = blockIdx.y;
  const int c = blockIdx.z;
  const float dec0 = expf(td[e]);
  const float dec1 = expf(td[e + 1]);
  const size_t ci = (size_t)(c * kB + b) * kD + e;
  const float2 ni = *(const float2*)&g_inum[ci];
  const float2 di = *(const float2*)&g_iden[ci];
  float n0 = ni.x, n1 = ni.y, d0 = di.x, d1 = di.y;
  size_t base = (size_t)(b * kS + c * kCLen) * kD + e;
#pragma unroll 4
  for (int i = 0; i < kCLen; i++) {
    const float2 kk = __ldcs((const float2*)&g_k[base]);
    const float2 ww = __ldcs((const float2*)&g_w[base]);
    const __half2 vh = __ldcs((const __half2*)&g_vh[base]);
    const __half2 rh = __ldcs((const __half2*)&g_rh[base]);
    const float2 vf = __half22float2(vh);
    const float2 rf = __half22float2(rh);
    const float ew0 = expf(kk.x - expf(ww.x));
    const float ew1 = expf(kk.y - expf(ww.y));
    n0 = fmaf(dec0, n0, ew0 * vf.x);
    n1 = fmaf(dec1, n1, ew1 * vf.y);
    d0 = fmaf(dec0, d0, ew0);
    d1 = fmaf(dec1, d1, ew1);
    const float y0 = rf.x * (n0 / (d0 + 1e-8f));
    const float y1 = rf.y * (n1 / (d1 + 1e-8f));
    __stcs((__half2*)&g_yh[base], __floats2half2_rn(y0, y1));
    base += kD;
  }
}

// ---------------------------------------------------------------------------
extern "C" void kernel_launch(void* const* d_in, const int* in_sizes, int n_in,
                              void* d_out, int out_size) {
  const float* x = (const float*)d_in[0];
  Ptr5 wp;
  for (int i = 0; i < 5; i++) wp.p[i] = (const float*)d_in[i + 1];
  const float* td = (const float*)d_in[6];
  float* out = (float*)d_out;

  float *pw, *pk;
  cudaGetSymbolAddress((void**)&pw, g_w);
  cudaGetSymbolAddress((void**)&pk, g_k);
  __half *prh, *pvh, *xh, *yh, *wh;
  cudaGetSymbolAddress((void**)&prh, g_rh);
  cudaGetSymbolAddress((void**)&pvh, g_vh);
  cudaGetSymbolAddress((void**)&xh, g_xh);
  cudaGetSymbolAddress((void**)&yh, g_yh);
  cudaGetSymbolAddress((void**)&wh, g_wh);

  cudaFuncSetAttribute(gemm_fused, cudaFuncAttributeMaxDynamicSharedMemorySize,
                       SMEM_BYTES);
  cudaFuncSetAttribute(gemm_one, cudaFuncAttributeMaxDynamicSharedMemorySize,
                       SMEM_BYTES);

  cvt_all<<<dim3(2048, 1, 6), 256>>>(x, wp, (__half2*)xh, (__half2*)wh);

  Proj4 p;
  p.W[0] = wh + 0 * (size_t)kD * kD;  // Wr
  p.W[1] = wh + 1 * (size_t)kD * kD;  // Ww
  p.W[2] = wh + 2 * (size_t)kD * kD;  // Wk
  p.W[3] = wh + 3 * (size_t)kD * kD;  // Wv
  p.C[0] = prh; p.C[1] = pw; p.C[2] = pk; p.C[3] = pvh;
  const __half* Wo = wh + 4 * (size_t)kD * kD;

  gemm_fused<<<dim3(4 * NTILES, kM / BM), NTHR, SMEM_BYTES>>>(xh, p);

  dim3 gs(kD / 512, kB, kChunks);  // 2 channels per thread
  scan_partial<<<gs, 256>>>(td);
  // One warp per channel: kB*kD warps = kB*kD/8 blocks of 256 threads.
  scan_carry<<<kB * kD / 8, 256>>>(td, out);
  scan_final<<<gs, 256>>>(td);

  gemm_one<<<dim3(NTILES, kM / BM), NTHR, SMEM_BYTES>>>(yh, Wo, out);
}